// round 2
// baseline (speedup 1.0000x reference)
#include <cuda_runtime.h>
#include <cuda_bf16.h>
#include <cstdint>

#define DINLINE __device__ __forceinline__

static constexpr int M_TOT = 8192;
static constexpr int N_TOT = 4096;
static constexpr int K_TOT = 4096;

static constexpr int BM = 128;
static constexpr int BN = 128;
static constexpr int BK = 64;                 // bf16 elems per k-chunk (128B rows)
static constexpr int NK = K_TOT / BK;         // 64 mainloop iterations

static constexpr int TILE_BYTES  = BM * BK * 2;        // 16384 (one operand tile)
static constexpr int STAGE_BYTES = 4 * TILE_BYTES;     // Ahi,Alo,Bhi,Blo = 65536
static constexpr int NSTAGE = 3;
static constexpr int SMEM_TOTAL = NSTAGE * STAGE_BYTES; // 196608

// ------------------- scratch (device globals; no allocation) -------------------
__device__ __align__(128) __nv_bfloat16 g_xhi[(size_t)M_TOT * K_TOT];
__device__ __align__(128) __nv_bfloat16 g_xlo[(size_t)M_TOT * K_TOT];
__device__ __align__(128) __nv_bfloat16 g_whi[(size_t)N_TOT * K_TOT];
__device__ __align__(128) __nv_bfloat16 g_wlo[(size_t)N_TOT * K_TOT];

// ------------------- PTX helpers (all sm_80-base features) -------------------
DINLINE uint32_t smem_u32(const void* p) {
    uint32_t a;
    asm("{ .reg .u64 t; cvta.to.shared.u64 t, %1; cvt.u32.u64 %0, t; }" : "=r"(a) : "l"(p));
    return a;
}
DINLINE void cp16(uint32_t dst, const void* src) {
    asm volatile("cp.async.cg.shared.global [%0], [%1], 16;" :: "r"(dst), "l"(src) : "memory");
}
DINLINE void cp_commit() { asm volatile("cp.async.commit_group;" ::: "memory"); }
template <int N> DINLINE void cp_wait() {
    asm volatile("cp.async.wait_group %0;" :: "n"(N) : "memory");
}
DINLINE void ldsm_x4(uint32_t* r, uint32_t addr) {
    asm volatile("ldmatrix.sync.aligned.m8n8.x4.shared.b16 {%0,%1,%2,%3}, [%4];"
                 : "=r"(r[0]), "=r"(r[1]), "=r"(r[2]), "=r"(r[3]) : "r"(addr));
}
DINLINE void mma_bf16(float* d, const uint32_t* a, uint32_t b0, uint32_t b1) {
    asm volatile(
        "mma.sync.aligned.m16n8k16.row.col.f32.bf16.bf16.f32 "
        "{%0,%1,%2,%3}, {%4,%5,%6,%7}, {%8,%9}, {%0,%1,%2,%3};"
        : "+f"(d[0]), "+f"(d[1]), "+f"(d[2]), "+f"(d[3])
        : "r"(a[0]), "r"(a[1]), "r"(a[2]), "r"(a[3]), "r"(b0), "r"(b1));
}

// ------------------- prep: fp32 -> (hi, lo) bf16, row-major -------------------
DINLINE uint32_t pack_bf2(__nv_bfloat16 a, __nv_bfloat16 b) {
    return (uint32_t)__bfloat16_as_ushort(a) | ((uint32_t)__bfloat16_as_ushort(b) << 16);
}
__global__ void __launch_bounds__(256) prep_kernel(const float* __restrict__ src,
                                                   __nv_bfloat16* __restrict__ dhi,
                                                   __nv_bfloat16* __restrict__ dlo) {
    size_t i8 = ((size_t)blockIdx.x * 256u + threadIdx.x) * 8u;
    const float4* p = reinterpret_cast<const float4*>(src + i8);
    float4 v0 = p[0], v1 = p[1];
    float v[8] = {v0.x, v0.y, v0.z, v0.w, v1.x, v1.y, v1.z, v1.w};
    uint32_t ph[4], pl[4];
#pragma unroll
    for (int i = 0; i < 4; i++) {
        float a = v[2 * i], b = v[2 * i + 1];
        __nv_bfloat16 h0 = __float2bfloat16(a);
        __nv_bfloat16 h1 = __float2bfloat16(b);
        __nv_bfloat16 l0 = __float2bfloat16(a - __bfloat162float(h0));
        __nv_bfloat16 l1 = __float2bfloat16(b - __bfloat162float(h1));
        ph[i] = pack_bf2(h0, h1);
        pl[i] = pack_bf2(l0, l1);
    }
    *reinterpret_cast<uint4*>(dhi + i8) = make_uint4(ph[0], ph[1], ph[2], ph[3]);
    *reinterpret_cast<uint4*>(dlo + i8) = make_uint4(pl[0], pl[1], pl[2], pl[3]);
}

// ------------------- GEMM: 128x128 CTA tile, bf16x3, mma.sync, 3-stage cp.async -------------------
__global__ void __launch_bounds__(256, 1) gemm_bf16x3_kernel(float* __restrict__ out) {
    extern __shared__ char smem[];
    const uint32_t sb = smem_u32(smem);
    const int tid  = threadIdx.x;
    const int wid  = tid >> 5;
    const int lane = tid & 31;
    const int wm = wid >> 2;        // 0..1  (M dir, 64 rows each)
    const int wn = wid & 3;         // 0..3  (N dir, 32 cols each)
    const int mbase = blockIdx.y * BM;
    const int nbase = blockIdx.x * BN;

    // per-thread load geometry: 8 chunks of 16B per 128B row
    const int lr = tid >> 3;        // 0..31 (row group)
    const int lc = tid & 7;         // chunk index

    auto load_stage = [&](int kt, int stg) {
        const uint32_t s0 = sb + stg * STAGE_BYTES;
        const size_t gk = (size_t)kt * BK + (size_t)lc * 8;
#pragma unroll
        for (int i = 0; i < 4; i++) {
            const int row = lr + i * 32;
            const uint32_t d = (uint32_t)row * 128u + (uint32_t)((lc ^ (row & 7)) << 4);
            const size_t ga = (size_t)(mbase + row) * K_TOT + gk;
            const size_t gb = (size_t)(nbase + row) * K_TOT + gk;
            cp16(s0 + d,                 g_xhi + ga);
            cp16(s0 + TILE_BYTES + d,     g_xlo + ga);
            cp16(s0 + 2 * TILE_BYTES + d, g_whi + gb);
            cp16(s0 + 3 * TILE_BYTES + d, g_wlo + gb);
        }
    };

    float acc[4][4][4];
#pragma unroll
    for (int a = 0; a < 4; a++)
#pragma unroll
        for (int b = 0; b < 4; b++)
#pragma unroll
            for (int c = 0; c < 4; c++) acc[a][b][c] = 0.0f;

    load_stage(0, 0);
    cp_commit();
    load_stage(1, 1);
    cp_commit();

    // ldmatrix addressing (lane-invariant parts)
    const uint32_t a_lrow  = (uint32_t)(lane & 15);
    const uint32_t a_lchnk = (uint32_t)(lane >> 4);          // 0/1 -> k half
    const uint32_t b_lrow  = (uint32_t)((lane & 7) + ((lane >> 4) << 3));
    const uint32_t b_lchnk = (uint32_t)((lane >> 3) & 1);

    int stg = 0;
#pragma unroll 1
    for (int kt = 0; kt < NK; kt++) {
        cp_wait<1>();
        __syncthreads();
        if (kt + 2 < NK) {
            int ns = stg + 2; if (ns >= NSTAGE) ns -= NSTAGE;
            load_stage(kt + 2, ns);
        }
        cp_commit();

        const uint32_t base = sb + stg * STAGE_BYTES;
#pragma unroll
        for (int s = 0; s < 4; s++) {                       // four k16 slices of BK=64
            uint32_t ah[4][4], al[4][4];
            const uint32_t achunk = 2u * s + a_lchnk;
#pragma unroll
            for (int mf = 0; mf < 4; mf++) {
                const uint32_t row = (uint32_t)(wm * 64 + mf * 16) + a_lrow;
                const uint32_t addr = base + row * 128u + ((achunk ^ (row & 7)) << 4);
                ldsm_x4(ah[mf], addr);
                ldsm_x4(al[mf], addr + TILE_BYTES);
            }
            uint32_t bh[8], bl[8];
            const uint32_t bchunk = 2u * s + b_lchnk;
#pragma unroll
            for (int p = 0; p < 2; p++) {
                const uint32_t row = (uint32_t)(wn * 32 + p * 16) + b_lrow;
                const uint32_t addr = base + 2 * TILE_BYTES + row * 128u + ((bchunk ^ (row & 7)) << 4);
                ldsm_x4(&bh[p * 4], addr);
                ldsm_x4(&bl[p * 4], addr + TILE_BYTES);
            }
#pragma unroll
            for (int mf = 0; mf < 4; mf++) {
#pragma unroll
                for (int nf = 0; nf < 4; nf++) {
                    const int p = nf >> 1, q = nf & 1;
                    const uint32_t b0h = bh[p * 4 + 2 * q], b1h = bh[p * 4 + 2 * q + 1];
                    const uint32_t b0l = bl[p * 4 + 2 * q], b1l = bl[p * 4 + 2 * q + 1];
                    mma_bf16(acc[mf][nf], ah[mf], b0h, b1h);   // hi * hi
                    mma_bf16(acc[mf][nf], ah[mf], b0l, b1l);   // hi * lo
                    mma_bf16(acc[mf][nf], al[mf], b0h, b1h);   // lo * hi
                }
            }
        }
        stg++; if (stg >= NSTAGE) stg = 0;
    }

    // ------------------- epilogue -------------------
    const int gid = lane >> 2;          // 0..7 (row in frag)
    const int tg  = lane & 3;           // 0..3 (col pair)
    float* ob = out + (size_t)mbase * N_TOT + nbase;
#pragma unroll
    for (int mf = 0; mf < 4; mf++) {
#pragma unroll
        for (int nf = 0; nf < 4; nf++) {
            const int r = wm * 64 + mf * 16 + gid;
            const int c = wn * 32 + nf * 8 + tg * 2;
            *reinterpret_cast<float2*>(ob + (size_t)r * N_TOT + c) =
                make_float2(acc[mf][nf][0], acc[mf][nf][1]);
            *reinterpret_cast<float2*>(ob + (size_t)(r + 8) * N_TOT + c) =
                make_float2(acc[mf][nf][2], acc[mf][nf][3]);
        }
    }
}

// ------------------- launch -------------------
extern "C" void kernel_launch(void* const* d_in, const int* in_sizes, int n_in,
                              void* d_out, int out_size) {
    const float* x = (const float*)d_in[0];
    const float* w = (const float*)d_in[1];
    // robustness: identify tensors by element count (x: 8192*4096=33.5M, w: 4096*4096=16.8M)
    if (n_in >= 2 && in_sizes[0] == N_TOT * K_TOT) {
        x = (const float*)d_in[1];
        w = (const float*)d_in[0];
    }
    float* out = (float*)d_out;

    __nv_bfloat16 *xhi, *xlo, *whi, *wlo;
    cudaGetSymbolAddress((void**)&xhi, g_xhi);
    cudaGetSymbolAddress((void**)&xlo, g_xlo);
    cudaGetSymbolAddress((void**)&whi, g_whi);
    cudaGetSymbolAddress((void**)&wlo, g_wlo);

    prep_kernel<<<(int)(((size_t)M_TOT * K_TOT / 8) / 256), 256>>>(x, xhi, xlo);
    prep_kernel<<<(int)(((size_t)N_TOT * K_TOT / 8) / 256), 256>>>(w, whi, wlo);

    cudaFuncSetAttribute(gemm_bf16x3_kernel,
                         cudaFuncAttributeMaxDynamicSharedMemorySize, SMEM_TOTAL);
    gemm_bf16x3_kernel<<<dim3(N_TOT / BN, M_TOT / BM), 256, SMEM_TOTAL>>>(out);
}

// round 3
// speedup vs baseline: 1.4293x; 1.4293x over previous
#include <cuda_runtime.h>
#include <cuda_fp16.h>
#include <cuda_bf16.h>
#include <cstdint>

#define DINLINE __device__ __forceinline__

static constexpr int M_TOT = 8192;
static constexpr int N_TOT = 4096;
static constexpr int K_TOT = 4096;

static constexpr int BM = 128;
static constexpr int BN = 128;
static constexpr int BK = 64;                 // fp16 elems per k-chunk (128B rows)
static constexpr int NK = K_TOT / BK;         // 64 mainloop iterations

static constexpr int TILE_BYTES  = BM * BK * 2;        // 16384 per operand tile
static constexpr int STAGE_BYTES = 3 * TILE_BYTES;     // A(xh), B(wh), B(wl) = 49152
static constexpr int NSTAGE = 4;
static constexpr int SMEM_TOTAL = NSTAGE * STAGE_BYTES; // 196608

// ------------------- scratch (device globals; no allocation) -------------------
__device__ __align__(128) __half g_xh[(size_t)M_TOT * K_TOT];   // 64 MB
__device__ __align__(128) __half g_wh[(size_t)N_TOT * K_TOT];   // 32 MB
__device__ __align__(128) __half g_wl[(size_t)N_TOT * K_TOT];   // 32 MB

// ------------------- PTX helpers (sm_80-base features only) -------------------
DINLINE uint32_t smem_u32(const void* p) {
    uint32_t a;
    asm("{ .reg .u64 t; cvta.to.shared.u64 t, %1; cvt.u32.u64 %0, t; }" : "=r"(a) : "l"(p));
    return a;
}
DINLINE void cp16(uint32_t dst, const void* src) {
    asm volatile("cp.async.cg.shared.global [%0], [%1], 16;" :: "r"(dst), "l"(src) : "memory");
}
DINLINE void cp_commit() { asm volatile("cp.async.commit_group;" ::: "memory"); }
template <int N> DINLINE void cp_wait() {
    asm volatile("cp.async.wait_group %0;" :: "n"(N) : "memory");
}
DINLINE void ldsm_x4(uint32_t* r, uint32_t addr) {
    asm volatile("ldmatrix.sync.aligned.m8n8.x4.shared.b16 {%0,%1,%2,%3}, [%4];"
                 : "=r"(r[0]), "=r"(r[1]), "=r"(r[2]), "=r"(r[3]) : "r"(addr));
}
DINLINE void mma_f16(float* d, const uint32_t* a, uint32_t b0, uint32_t b1) {
    asm volatile(
        "mma.sync.aligned.m16n8k16.row.col.f32.f16.f16.f32 "
        "{%0,%1,%2,%3}, {%4,%5,%6,%7}, {%8,%9}, {%0,%1,%2,%3};"
        : "+f"(d[0]), "+f"(d[1]), "+f"(d[2]), "+f"(d[3])
        : "r"(a[0]), "r"(a[1]), "r"(a[2]), "r"(a[3]), "r"(b0), "r"(b1));
}

// ------------------- prep kernels -------------------
DINLINE uint32_t pack_h2(__half a, __half b) {
    return (uint32_t)__half_as_ushort(a) | ((uint32_t)__half_as_ushort(b) << 16);
}
// x: fp32 -> fp16 (round once)
__global__ void __launch_bounds__(256) prep_x_kernel(const float* __restrict__ src,
                                                     __half* __restrict__ dst) {
    size_t i8 = ((size_t)blockIdx.x * 256u + threadIdx.x) * 8u;
    const float4* p = reinterpret_cast<const float4*>(src + i8);
    float4 v0 = p[0], v1 = p[1];
    float v[8] = {v0.x, v0.y, v0.z, v0.w, v1.x, v1.y, v1.z, v1.w};
    uint32_t ph[4];
#pragma unroll
    for (int i = 0; i < 4; i++)
        ph[i] = pack_h2(__float2half_rn(v[2 * i]), __float2half_rn(v[2 * i + 1]));
    *reinterpret_cast<uint4*>(dst + i8) = make_uint4(ph[0], ph[1], ph[2], ph[3]);
}
// w: fp32 -> (hi, lo) fp16 split
__global__ void __launch_bounds__(256) prep_w_kernel(const float* __restrict__ src,
                                                     __half* __restrict__ dhi,
                                                     __half* __restrict__ dlo) {
    size_t i8 = ((size_t)blockIdx.x * 256u + threadIdx.x) * 8u;
    const float4* p = reinterpret_cast<const float4*>(src + i8);
    float4 v0 = p[0], v1 = p[1];
    float v[8] = {v0.x, v0.y, v0.z, v0.w, v1.x, v1.y, v1.z, v1.w};
    uint32_t ph[4], pl[4];
#pragma unroll
    for (int i = 0; i < 4; i++) {
        float a = v[2 * i], b = v[2 * i + 1];
        __half h0 = __float2half_rn(a);
        __half h1 = __float2half_rn(b);
        __half l0 = __float2half_rn(a - __half2float(h0));
        __half l1 = __float2half_rn(b - __half2float(h1));
        ph[i] = pack_h2(h0, h1);
        pl[i] = pack_h2(l0, l1);
    }
    *reinterpret_cast<uint4*>(dhi + i8) = make_uint4(ph[0], ph[1], ph[2], ph[3]);
    *reinterpret_cast<uint4*>(dlo + i8) = make_uint4(pl[0], pl[1], pl[2], pl[3]);
}

// ------------------- GEMM: 128x128 CTA tile, fp16x2, mma.sync, 4-stage cp.async -------------------
__global__ void __launch_bounds__(256, 1) gemm_fp16x2_kernel(float* __restrict__ out) {
    extern __shared__ char smem[];
    const uint32_t sb = smem_u32(smem);
    const int tid  = threadIdx.x;
    const int wid  = tid >> 5;
    const int lane = tid & 31;
    const int wm = wid >> 2;        // 0..1  (M dir, 64 rows each)
    const int wn = wid & 3;         // 0..3  (N dir, 32 cols each)
    const int mbase = blockIdx.y * BM;
    const int nbase = blockIdx.x * BN;

    // per-thread load geometry: 8 chunks of 16B per 128B row
    const int lr = tid >> 3;        // 0..31 (row group)
    const int lc = tid & 7;         // chunk index

    auto load_stage = [&](int kt, int stg) {
        const uint32_t s0 = sb + stg * STAGE_BYTES;
        const size_t gk = (size_t)kt * BK + (size_t)lc * 8;
#pragma unroll
        for (int i = 0; i < 4; i++) {
            const int row = lr + i * 32;
            const uint32_t d = (uint32_t)row * 128u + (uint32_t)((lc ^ (row & 7)) << 4);
            const size_t ga = (size_t)(mbase + row) * K_TOT + gk;
            const size_t gb = (size_t)(nbase + row) * K_TOT + gk;
            cp16(s0 + d,                  g_xh + ga);
            cp16(s0 + TILE_BYTES + d,     g_wh + gb);
            cp16(s0 + 2 * TILE_BYTES + d, g_wl + gb);
        }
    };

    float acc[4][4][4];
#pragma unroll
    for (int a = 0; a < 4; a++)
#pragma unroll
        for (int b = 0; b < 4; b++)
#pragma unroll
            for (int c = 0; c < 4; c++) acc[a][b][c] = 0.0f;

    load_stage(0, 0); cp_commit();
    load_stage(1, 1); cp_commit();
    load_stage(2, 2); cp_commit();

    // ldmatrix addressing (lane-dependent parts)
    const uint32_t a_lrow  = (uint32_t)(lane & 15);
    const uint32_t a_lchnk = (uint32_t)(lane >> 4);          // 0/1 -> k half
    const uint32_t b_lrow  = (uint32_t)((lane & 7) + ((lane >> 4) << 3));
    const uint32_t b_lchnk = (uint32_t)((lane >> 3) & 1);

    int stg = 0;
#pragma unroll 1
    for (int kt = 0; kt < NK; kt++) {
        cp_wait<2>();
        __syncthreads();
        if (kt + 3 < NK) {
            int ns = stg + 3; if (ns >= NSTAGE) ns -= NSTAGE;
            load_stage(kt + 3, ns);
        }
        cp_commit();

        const uint32_t base = sb + stg * STAGE_BYTES;
#pragma unroll
        for (int s = 0; s < 4; s++) {                       // four k16 slices of BK=64
            uint32_t ah[4][4];
            const uint32_t achunk = 2u * s + a_lchnk;
#pragma unroll
            for (int mf = 0; mf < 4; mf++) {
                const uint32_t row = (uint32_t)(wm * 64 + mf * 16) + a_lrow;
                const uint32_t addr = base + row * 128u + ((achunk ^ (row & 7)) << 4);
                ldsm_x4(ah[mf], addr);
            }
            uint32_t bh[8], bl[8];
            const uint32_t bchunk = 2u * s + b_lchnk;
#pragma unroll
            for (int p = 0; p < 2; p++) {
                const uint32_t row = (uint32_t)(wn * 32 + p * 16) + b_lrow;
                const uint32_t addr = base + TILE_BYTES + row * 128u + ((bchunk ^ (row & 7)) << 4);
                ldsm_x4(&bh[p * 4], addr);
                ldsm_x4(&bl[p * 4], addr + TILE_BYTES);
            }
#pragma unroll
            for (int mf = 0; mf < 4; mf++) {
#pragma unroll
                for (int nf = 0; nf < 4; nf++) {
                    const int p = nf >> 1, q = nf & 1;
                    mma_f16(acc[mf][nf], ah[mf], bh[p * 4 + 2 * q], bh[p * 4 + 2 * q + 1]); // xh*wh
                    mma_f16(acc[mf][nf], ah[mf], bl[p * 4 + 2 * q], bl[p * 4 + 2 * q + 1]); // xh*wl
                }
            }
        }
        stg++; if (stg >= NSTAGE) stg = 0;
    }

    // ------------------- epilogue -------------------
    const int gid = lane >> 2;          // 0..7 (row in frag)
    const int tg  = lane & 3;           // 0..3 (col pair)
    float* ob = out + (size_t)mbase * N_TOT + nbase;
#pragma unroll
    for (int mf = 0; mf < 4; mf++) {
#pragma unroll
        for (int nf = 0; nf < 4; nf++) {
            const int r = wm * 64 + mf * 16 + gid;
            const int c = wn * 32 + nf * 8 + tg * 2;
            *reinterpret_cast<float2*>(ob + (size_t)r * N_TOT + c) =
                make_float2(acc[mf][nf][0], acc[mf][nf][1]);
            *reinterpret_cast<float2*>(ob + (size_t)(r + 8) * N_TOT + c) =
                make_float2(acc[mf][nf][2], acc[mf][nf][3]);
        }
    }
}

// ------------------- launch -------------------
extern "C" void kernel_launch(void* const* d_in, const int* in_sizes, int n_in,
                              void* d_out, int out_size) {
    const float* x = (const float*)d_in[0];
    const float* w = (const float*)d_in[1];
    // robustness: identify tensors by element count (x: 8192*4096=33.5M, w: 4096*4096=16.8M)
    if (n_in >= 2 && in_sizes[0] == N_TOT * K_TOT) {
        x = (const float*)d_in[1];
        w = (const float*)d_in[0];
    }
    float* out = (float*)d_out;

    __half *xh, *wh, *wl;
    cudaGetSymbolAddress((void**)&xh, g_xh);
    cudaGetSymbolAddress((void**)&wh, g_wh);
    cudaGetSymbolAddress((void**)&wl, g_wl);

    prep_x_kernel<<<(int)(((size_t)M_TOT * K_TOT / 8) / 256), 256>>>(x, xh);
    prep_w_kernel<<<(int)(((size_t)N_TOT * K_TOT / 8) / 256), 256>>>(w, wh, wl);

    cudaFuncSetAttribute(gemm_fp16x2_kernel,
                         cudaFuncAttributeMaxDynamicSharedMemorySize, SMEM_TOTAL);
    gemm_fp16x2_kernel<<<dim3(N_TOT / BN, M_TOT / BM), 256, SMEM_TOTAL>>>(out);
}

// round 4
// speedup vs baseline: 2.3399x; 1.6371x over previous
#include <cuda_runtime.h>
#include <cuda_fp16.h>
#include <cstdint>

#define DINLINE __device__ __forceinline__

static constexpr int M_TOT = 8192;
static constexpr int N_TOT = 4096;
static constexpr int K_TOT = 4096;

static constexpr int BM = 128;
static constexpr int BN = 128;
static constexpr int BK = 64;                 // fp16 elems per k-chunk (128B rows)
static constexpr int NK = K_TOT / BK;         // 64 mainloop iterations

static constexpr int TILE_BYTES  = BM * BK * 2;        // 16384 per operand tile
static constexpr int STAGE_BYTES = 2 * TILE_BYTES;     // A(xh), B(wh) = 32768
static constexpr int NSTAGE = 5;
static constexpr int SMEM_TOTAL = NSTAGE * STAGE_BYTES; // 163840

// ------------------- scratch (device globals; no allocation) -------------------
__device__ __align__(128) __half g_xh[(size_t)M_TOT * K_TOT];   // 64 MB
__device__ __align__(128) __half g_wh[(size_t)N_TOT * K_TOT];   // 32 MB

// ------------------- PTX helpers (sm_80-base features only) -------------------
DINLINE uint32_t smem_u32(const void* p) {
    uint32_t a;
    asm("{ .reg .u64 t; cvta.to.shared.u64 t, %1; cvt.u32.u64 %0, t; }" : "=r"(a) : "l"(p));
    return a;
}
DINLINE void cp16(uint32_t dst, const void* src) {
    asm volatile("cp.async.cg.shared.global [%0], [%1], 16;" :: "r"(dst), "l"(src) : "memory");
}
DINLINE void cp_commit() { asm volatile("cp.async.commit_group;" ::: "memory"); }
template <int N> DINLINE void cp_wait() {
    asm volatile("cp.async.wait_group %0;" :: "n"(N) : "memory");
}
DINLINE void ldsm_x4(uint32_t* r, uint32_t addr) {
    asm volatile("ldmatrix.sync.aligned.m8n8.x4.shared.b16 {%0,%1,%2,%3}, [%4];"
                 : "=r"(r[0]), "=r"(r[1]), "=r"(r[2]), "=r"(r[3]) : "r"(addr));
}
DINLINE void mma_f16(float* d, const uint32_t* a, uint32_t b0, uint32_t b1) {
    asm volatile(
        "mma.sync.aligned.m16n8k16.row.col.f32.f16.f16.f32 "
        "{%0,%1,%2,%3}, {%4,%5,%6,%7}, {%8,%9}, {%0,%1,%2,%3};"
        : "+f"(d[0]), "+f"(d[1]), "+f"(d[2]), "+f"(d[3])
        : "r"(a[0]), "r"(a[1]), "r"(a[2]), "r"(a[3]), "r"(b0), "r"(b1));
}

// ------------------- prep: fp32 -> fp16 (round to nearest) -------------------
DINLINE uint32_t pack_h2(__half a, __half b) {
    return (uint32_t)__half_as_ushort(a) | ((uint32_t)__half_as_ushort(b) << 16);
}
__global__ void __launch_bounds__(256) prep_kernel(const float* __restrict__ src,
                                                   __half* __restrict__ dst) {
    size_t i8 = ((size_t)blockIdx.x * 256u + threadIdx.x) * 8u;
    const float4* p = reinterpret_cast<const float4*>(src + i8);
    float4 v0 = p[0], v1 = p[1];
    uint32_t ph[4];
    ph[0] = pack_h2(__float2half_rn(v0.x), __float2half_rn(v0.y));
    ph[1] = pack_h2(__float2half_rn(v0.z), __float2half_rn(v0.w));
    ph[2] = pack_h2(__float2half_rn(v1.x), __float2half_rn(v1.y));
    ph[3] = pack_h2(__float2half_rn(v1.z), __float2half_rn(v1.w));
    *reinterpret_cast<uint4*>(dst + i8) = make_uint4(ph[0], ph[1], ph[2], ph[3]);
}

// ------------------- GEMM: 128x128 CTA tile, fp16 single-term, 5-stage cp.async -------------------
__global__ void __launch_bounds__(256, 1) gemm_fp16_kernel(float* __restrict__ out) {
    extern __shared__ char smem[];
    const uint32_t sb = smem_u32(smem);
    const int tid  = threadIdx.x;
    const int wid  = tid >> 5;
    const int lane = tid & 31;
    const int wm = wid >> 2;        // 0..1  (M dir, 64 rows each)
    const int wn = wid & 3;         // 0..3  (N dir, 32 cols each)
    const int mbase = blockIdx.y * BM;
    const int nbase = blockIdx.x * BN;

    // per-thread load geometry: 8 chunks of 16B per 128B row
    const int lr = tid >> 3;        // 0..31 (row group)
    const int lc = tid & 7;         // chunk index

    auto load_stage = [&](int kt, int stg) {
        const uint32_t s0 = sb + stg * STAGE_BYTES;
        const size_t gk = (size_t)kt * BK + (size_t)lc * 8;
#pragma unroll
        for (int i = 0; i < 4; i++) {
            const int row = lr + i * 32;
            const uint32_t d = (uint32_t)row * 128u + (uint32_t)((lc ^ (row & 7)) << 4);
            cp16(s0 + d,              g_xh + (size_t)(mbase + row) * K_TOT + gk);
            cp16(s0 + TILE_BYTES + d, g_wh + (size_t)(nbase + row) * K_TOT + gk);
        }
    };

    float acc[4][4][4];
#pragma unroll
    for (int a = 0; a < 4; a++)
#pragma unroll
        for (int b = 0; b < 4; b++)
#pragma unroll
            for (int c = 0; c < 4; c++) acc[a][b][c] = 0.0f;

    load_stage(0, 0); cp_commit();
    load_stage(1, 1); cp_commit();
    load_stage(2, 2); cp_commit();
    load_stage(3, 3); cp_commit();

    // ldmatrix addressing (lane-dependent parts)
    const uint32_t a_lrow  = (uint32_t)(lane & 15);
    const uint32_t a_lchnk = (uint32_t)(lane >> 4);          // 0/1 -> k half
    const uint32_t b_lrow  = (uint32_t)((lane & 7) + ((lane >> 4) << 3));
    const uint32_t b_lchnk = (uint32_t)((lane >> 3) & 1);

    int stg = 0;
#pragma unroll 1
    for (int kt = 0; kt < NK; kt++) {
        cp_wait<3>();
        __syncthreads();
        if (kt + 4 < NK) {
            int ns = stg + 4; if (ns >= NSTAGE) ns -= NSTAGE;
            load_stage(kt + 4, ns);
        }
        cp_commit();

        const uint32_t base = sb + stg * STAGE_BYTES;
#pragma unroll
        for (int s = 0; s < 4; s++) {                       // four k16 slices of BK=64
            uint32_t ah[4][4];
            const uint32_t achunk = 2u * s + a_lchnk;
#pragma unroll
            for (int mf = 0; mf < 4; mf++) {
                const uint32_t row = (uint32_t)(wm * 64 + mf * 16) + a_lrow;
                const uint32_t addr = base + row * 128u + ((achunk ^ (row & 7)) << 4);
                ldsm_x4(ah[mf], addr);
            }
            uint32_t bh[8];
            const uint32_t bchunk = 2u * s + b_lchnk;
#pragma unroll
            for (int p = 0; p < 2; p++) {
                const uint32_t row = (uint32_t)(wn * 32 + p * 16) + b_lrow;
                const uint32_t addr = base + TILE_BYTES + row * 128u + ((bchunk ^ (row & 7)) << 4);
                ldsm_x4(&bh[p * 4], addr);
            }
#pragma unroll
            for (int mf = 0; mf < 4; mf++) {
#pragma unroll
                for (int nf = 0; nf < 4; nf++) {
                    const int p = nf >> 1, q = nf & 1;
                    mma_f16(acc[mf][nf], ah[mf], bh[p * 4 + 2 * q], bh[p * 4 + 2 * q + 1]);
                }
            }
        }
        stg++; if (stg >= NSTAGE) stg = 0;
    }

    // ------------------- epilogue -------------------
    const int gid = lane >> 2;          // 0..7 (row in frag)
    const int tg  = lane & 3;           // 0..3 (col pair)
    float* ob = out + (size_t)mbase * N_TOT + nbase;
#pragma unroll
    for (int mf = 0; mf < 4; mf++) {
#pragma unroll
        for (int nf = 0; nf < 4; nf++) {
            const int r = wm * 64 + mf * 16 + gid;
            const int c = wn * 32 + nf * 8 + tg * 2;
            *reinterpret_cast<float2*>(ob + (size_t)r * N_TOT + c) =
                make_float2(acc[mf][nf][0], acc[mf][nf][1]);
            *reinterpret_cast<float2*>(ob + (size_t)(r + 8) * N_TOT + c) =
                make_float2(acc[mf][nf][2], acc[mf][nf][3]);
        }
    }
}

// ------------------- launch -------------------
extern "C" void kernel_launch(void* const* d_in, const int* in_sizes, int n_in,
                              void* d_out, int out_size) {
    const float* x = (const float*)d_in[0];
    const float* w = (const float*)d_in[1];
    // robustness: identify tensors by element count (x: 8192*4096=33.5M, w: 4096*4096=16.8M)
    if (n_in >= 2 && in_sizes[0] == N_TOT * K_TOT) {
        x = (const float*)d_in[1];
        w = (const float*)d_in[0];
    }
    float* out = (float*)d_out;

    __half *xh, *wh;
    cudaGetSymbolAddress((void**)&xh, g_xh);
    cudaGetSymbolAddress((void**)&wh, g_wh);

    prep_kernel<<<(int)(((size_t)M_TOT * K_TOT / 8) / 256), 256>>>(x, xh);
    prep_kernel<<<(int)(((size_t)N_TOT * K_TOT / 8) / 256), 256>>>(w, wh);

    cudaFuncSetAttribute(gemm_fp16_kernel,
                         cudaFuncAttributeMaxDynamicSharedMemorySize, SMEM_TOTAL);
    gemm_fp16_kernel<<<dim3(N_TOT / BN, M_TOT / BM), 256, SMEM_TOTAL>>>(out);
}

// round 5
// speedup vs baseline: 2.6289x; 1.1235x over previous
#include <cuda_runtime.h>
#include <cuda_fp16.h>
#include <cstdint>

#define DINLINE __device__ __forceinline__

static constexpr int M_TOT = 8192;
static constexpr int N_TOT = 4096;
static constexpr int K_TOT = 4096;

static constexpr int BM = 128;
static constexpr int BN = 256;
static constexpr int BK = 64;                 // fp16 elems per k-chunk (128B rows)
static constexpr int NK = K_TOT / BK;         // 64 mainloop iterations

static constexpr int A_BYTES = BM * BK * 2;            // 16384
static constexpr int B_BYTES = BN * BK * 2;            // 32768
static constexpr int STAGE_BYTES = A_BYTES + B_BYTES;  // 49152
static constexpr int NSTAGE = 4;
static constexpr int SMEM_TOTAL = NSTAGE * STAGE_BYTES; // 196608

// ------------------- scratch (device globals; no allocation) -------------------
__device__ __align__(128) __half g_xh[(size_t)M_TOT * K_TOT];   // 64 MB
__device__ __align__(128) __half g_wh[(size_t)N_TOT * K_TOT];   // 32 MB

// ------------------- PTX helpers (sm_80-base features only) -------------------
DINLINE uint32_t smem_u32(const void* p) {
    uint32_t a;
    asm("{ .reg .u64 t; cvta.to.shared.u64 t, %1; cvt.u32.u64 %0, t; }" : "=r"(a) : "l"(p));
    return a;
}
DINLINE void cp16(uint32_t dst, const void* src) {
    asm volatile("cp.async.cg.shared.global [%0], [%1], 16;" :: "r"(dst), "l"(src) : "memory");
}
DINLINE void cp_commit() { asm volatile("cp.async.commit_group;" ::: "memory"); }
template <int N> DINLINE void cp_wait() {
    asm volatile("cp.async.wait_group %0;" :: "n"(N) : "memory");
}
DINLINE void ldsm_x4(uint32_t* r, uint32_t addr) {
    asm volatile("ldmatrix.sync.aligned.m8n8.x4.shared.b16 {%0,%1,%2,%3}, [%4];"
                 : "=r"(r[0]), "=r"(r[1]), "=r"(r[2]), "=r"(r[3]) : "r"(addr));
}
DINLINE void mma_f16(float* d, const uint32_t* a, uint32_t b0, uint32_t b1) {
    asm volatile(
        "mma.sync.aligned.m16n8k16.row.col.f32.f16.f16.f32 "
        "{%0,%1,%2,%3}, {%4,%5,%6,%7}, {%8,%9}, {%0,%1,%2,%3};"
        : "+f"(d[0]), "+f"(d[1]), "+f"(d[2]), "+f"(d[3])
        : "r"(a[0]), "r"(a[1]), "r"(a[2]), "r"(a[3]), "r"(b0), "r"(b1));
}

// ------------------- prep: fp32 -> fp16 (round to nearest) -------------------
DINLINE uint32_t pack_h2(__half a, __half b) {
    return (uint32_t)__half_as_ushort(a) | ((uint32_t)__half_as_ushort(b) << 16);
}
__global__ void __launch_bounds__(256) prep_kernel(const float* __restrict__ src,
                                                   __half* __restrict__ dst) {
    size_t i8 = ((size_t)blockIdx.x * 256u + threadIdx.x) * 8u;
    const float4* p = reinterpret_cast<const float4*>(src + i8);
    float4 v0 = p[0], v1 = p[1];
    uint32_t ph[4];
    ph[0] = pack_h2(__float2half_rn(v0.x), __float2half_rn(v0.y));
    ph[1] = pack_h2(__float2half_rn(v0.z), __float2half_rn(v0.w));
    ph[2] = pack_h2(__float2half_rn(v1.x), __float2half_rn(v1.y));
    ph[3] = pack_h2(__float2half_rn(v1.z), __float2half_rn(v1.w));
    *reinterpret_cast<uint4*>(dst + i8) = make_uint4(ph[0], ph[1], ph[2], ph[3]);
}

// ------------------- GEMM: 128x256 CTA tile, 8 warps of 64x64, 4-stage cp.async -------------------
__global__ void __launch_bounds__(256, 1) gemm_fp16_kernel(float* __restrict__ out) {
    extern __shared__ char smem[];
    const uint32_t sb = smem_u32(smem);
    const int tid  = threadIdx.x;
    const int wid  = tid >> 5;
    const int lane = tid & 31;
    const int wm = wid >> 2;        // 0..1  (M dir, 64 rows each)
    const int wn = wid & 3;         // 0..3  (N dir, 64 cols each)
    const int mbase = blockIdx.y * BM;
    const int nbase = blockIdx.x * BN;

    // per-thread load geometry: 16B chunks over 128B rows; 384 rows total per stage
    const int lr = tid >> 3;        // 0..31 (row group)
    const int lc = tid & 7;         // chunk index

    auto load_stage = [&](int kt, int stg) {
        const uint32_t s0 = sb + stg * STAGE_BYTES;
        const size_t gk = (size_t)kt * BK + (size_t)lc * 8;
#pragma unroll
        for (int i = 0; i < 4; i++) {   // A: 128 rows
            const int row = lr + i * 32;
            const uint32_t d = (uint32_t)row * 128u + (uint32_t)((lc ^ (row & 7)) << 4);
            cp16(s0 + d, g_xh + (size_t)(mbase + row) * K_TOT + gk);
        }
#pragma unroll
        for (int i = 0; i < 8; i++) {   // B: 256 rows
            const int row = lr + i * 32;
            const uint32_t d = (uint32_t)row * 128u + (uint32_t)((lc ^ (row & 7)) << 4);
            cp16(s0 + A_BYTES + d, g_wh + (size_t)(nbase + row) * K_TOT + gk);
        }
    };

    float acc[4][8][4];
#pragma unroll
    for (int a = 0; a < 4; a++)
#pragma unroll
        for (int b = 0; b < 8; b++)
#pragma unroll
            for (int c = 0; c < 4; c++) acc[a][b][c] = 0.0f;

    load_stage(0, 0); cp_commit();
    load_stage(1, 1); cp_commit();
    load_stage(2, 2); cp_commit();

    // ldmatrix addressing (lane-dependent parts)
    const uint32_t a_lrow  = (uint32_t)(lane & 15);
    const uint32_t a_lchnk = (uint32_t)(lane >> 4);          // 0/1 -> k half
    const uint32_t b_lrow  = (uint32_t)((lane & 7) + ((lane >> 4) << 3));
    const uint32_t b_lchnk = (uint32_t)((lane >> 3) & 1);

    int stg = 0;
#pragma unroll 1
    for (int kt = 0; kt < NK; kt++) {
        cp_wait<2>();
        __syncthreads();
        if (kt + 3 < NK) {
            int ns = stg + 3; if (ns >= NSTAGE) ns -= NSTAGE;
            load_stage(kt + 3, ns);
        }
        cp_commit();

        const uint32_t base = sb + stg * STAGE_BYTES;
#pragma unroll
        for (int s = 0; s < 4; s++) {                       // four k16 slices of BK=64
            uint32_t ah[4][4];
            const uint32_t achunk = 2u * s + a_lchnk;
#pragma unroll
            for (int mf = 0; mf < 4; mf++) {
                const uint32_t row = (uint32_t)(wm * 64 + mf * 16) + a_lrow;
                const uint32_t addr = base + row * 128u + ((achunk ^ (row & 7)) << 4);
                ldsm_x4(ah[mf], addr);
            }
            uint32_t bh[16];
            const uint32_t bchunk = 2u * s + b_lchnk;
#pragma unroll
            for (int p = 0; p < 4; p++) {
                const uint32_t row = (uint32_t)(wn * 64 + p * 16) + b_lrow;
                const uint32_t addr = base + A_BYTES + row * 128u + ((bchunk ^ (row & 7)) << 4);
                ldsm_x4(&bh[p * 4], addr);
            }
#pragma unroll
            for (int mf = 0; mf < 4; mf++) {
#pragma unroll
                for (int nf = 0; nf < 8; nf++) {
                    const int p = nf >> 1, q = nf & 1;
                    mma_f16(acc[mf][nf], ah[mf], bh[p * 4 + 2 * q], bh[p * 4 + 2 * q + 1]);
                }
            }
        }
        stg++; if (stg >= NSTAGE) stg = 0;
    }

    // ------------------- epilogue -------------------
    const int gid = lane >> 2;          // 0..7 (row in frag)
    const int tg  = lane & 3;           // 0..3 (col pair)
    float* ob = out + (size_t)mbase * N_TOT + nbase;
#pragma unroll
    for (int mf = 0; mf < 4; mf++) {
#pragma unroll
        for (int nf = 0; nf < 8; nf++) {
            const int r = wm * 64 + mf * 16 + gid;
            const int c = wn * 64 + nf * 8 + tg * 2;
            *reinterpret_cast<float2*>(ob + (size_t)r * N_TOT + c) =
                make_float2(acc[mf][nf][0], acc[mf][nf][1]);
            *reinterpret_cast<float2*>(ob + (size_t)(r + 8) * N_TOT + c) =
                make_float2(acc[mf][nf][2], acc[mf][nf][3]);
        }
    }
}

// ------------------- launch -------------------
extern "C" void kernel_launch(void* const* d_in, const int* in_sizes, int n_in,
                              void* d_out, int out_size) {
    const float* x = (const float*)d_in[0];
    const float* w = (const float*)d_in[1];
    // robustness: identify tensors by element count (x: 8192*4096=33.5M, w: 4096*4096=16.8M)
    if (n_in >= 2 && in_sizes[0] == N_TOT * K_TOT) {
        x = (const float*)d_in[1];
        w = (const float*)d_in[0];
    }
    float* out = (float*)d_out;

    __half *xh, *wh;
    cudaGetSymbolAddress((void**)&xh, g_xh);
    cudaGetSymbolAddress((void**)&wh, g_wh);

    prep_kernel<<<(int)(((size_t)M_TOT * K_TOT / 8) / 256), 256>>>(x, xh);
    prep_kernel<<<(int)(((size_t)N_TOT * K_TOT / 8) / 256), 256>>>(w, wh);

    cudaFuncSetAttribute(gemm_fp16_kernel,
                         cudaFuncAttributeMaxDynamicSharedMemorySize, SMEM_TOTAL);
    gemm_fp16_kernel<<<dim3(N_TOT / BN, M_TOT / BM), 256, SMEM_TOTAL>>>(out);
}

// round 6
// speedup vs baseline: 2.8243x; 1.0743x over previous
#include <cuda_runtime.h>
#include <cuda_fp16.h>
#include <cstdint>

#define DINLINE __device__ __forceinline__

static constexpr int M_TOT = 8192;
static constexpr int N_TOT = 4096;
static constexpr int K_TOT = 4096;

static constexpr int BM = 128;
static constexpr int BN = 128;
static constexpr int BK = 64;                 // fp16 elems per k-chunk (128B rows)
static constexpr int NK = K_TOT / BK;         // 64 mainloop iterations

static constexpr int TILE_BYTES  = BM * BK * 2;        // 16384 per operand tile
static constexpr int STAGE_BYTES = 2 * TILE_BYTES;     // 32768
static constexpr int NSTAGE = 3;
static constexpr int SMEM_TOTAL = NSTAGE * STAGE_BYTES; // 98304 per CTA (2 CTAs/SM)

// ------------------- scratch (device globals; no allocation) -------------------
__device__ __align__(128) __half g_xh[(size_t)M_TOT * K_TOT];   // 64 MB
__device__ __align__(128) __half g_wh[(size_t)N_TOT * K_TOT];   // 32 MB

// ------------------- PTX helpers (sm_80-base features only) -------------------
DINLINE uint32_t smem_u32(const void* p) {
    uint32_t a;
    asm("{ .reg .u64 t; cvta.to.shared.u64 t, %1; cvt.u32.u64 %0, t; }" : "=r"(a) : "l"(p));
    return a;
}
DINLINE void cp16(uint32_t dst, const void* src) {
    asm volatile("cp.async.cg.shared.global [%0], [%1], 16;" :: "r"(dst), "l"(src) : "memory");
}
DINLINE void cp_commit() { asm volatile("cp.async.commit_group;" ::: "memory"); }
template <int N> DINLINE void cp_wait() {
    asm volatile("cp.async.wait_group %0;" :: "n"(N) : "memory");
}
DINLINE void ldsm_x4(uint32_t* r, uint32_t addr) {
    asm volatile("ldmatrix.sync.aligned.m8n8.x4.shared.b16 {%0,%1,%2,%3}, [%4];"
                 : "=r"(r[0]), "=r"(r[1]), "=r"(r[2]), "=r"(r[3]) : "r"(addr));
}
DINLINE void mma_f16(float* d, const uint32_t* a, uint32_t b0, uint32_t b1) {
    asm volatile(
        "mma.sync.aligned.m16n8k16.row.col.f32.f16.f16.f32 "
        "{%0,%1,%2,%3}, {%4,%5,%6,%7}, {%8,%9}, {%0,%1,%2,%3};"
        : "+f"(d[0]), "+f"(d[1]), "+f"(d[2]), "+f"(d[3])
        : "r"(a[0]), "r"(a[1]), "r"(a[2]), "r"(a[3]), "r"(b0), "r"(b1));
}

// ------------------- prep: fp32 -> fp16 (round to nearest) -------------------
DINLINE uint32_t pack_h2(__half a, __half b) {
    return (uint32_t)__half_as_ushort(a) | ((uint32_t)__half_as_ushort(b) << 16);
}
__global__ void __launch_bounds__(256) prep_kernel(const float* __restrict__ src,
                                                   __half* __restrict__ dst) {
    size_t i8 = ((size_t)blockIdx.x * 256u + threadIdx.x) * 8u;
    const float4* p = reinterpret_cast<const float4*>(src + i8);
    float4 v0 = p[0], v1 = p[1];
    uint32_t ph[4];
    ph[0] = pack_h2(__float2half_rn(v0.x), __float2half_rn(v0.y));
    ph[1] = pack_h2(__float2half_rn(v0.z), __float2half_rn(v0.w));
    ph[2] = pack_h2(__float2half_rn(v1.x), __float2half_rn(v1.y));
    ph[3] = pack_h2(__float2half_rn(v1.z), __float2half_rn(v1.w));
    *reinterpret_cast<uint4*>(dst + i8) = make_uint4(ph[0], ph[1], ph[2], ph[3]);
}

// ------------------- GEMM: 128x128 CTA tile, 2 CTAs/SM, 3-stage cp.async -------------------
__global__ void __launch_bounds__(256, 2) gemm_fp16_kernel(float* __restrict__ out) {
    extern __shared__ char smem[];
    const uint32_t sb = smem_u32(smem);
    const int tid  = threadIdx.x;
    const int wid  = tid >> 5;
    const int lane = tid & 31;
    const int wm = wid >> 2;        // 0..1  (M dir, 64 rows each)
    const int wn = wid & 3;         // 0..3  (N dir, 32 cols each)
    const int mbase = blockIdx.y * BM;
    const int nbase = blockIdx.x * BN;

    // per-thread load geometry: 8 chunks of 16B per 128B row
    const int lr = tid >> 3;        // 0..31 (row group)
    const int lc = tid & 7;         // chunk index

    auto load_stage = [&](int kt, int stg) {
        const uint32_t s0 = sb + stg * STAGE_BYTES;
        const size_t gk = (size_t)kt * BK + (size_t)lc * 8;
#pragma unroll
        for (int i = 0; i < 4; i++) {
            const int row = lr + i * 32;
            const uint32_t d = (uint32_t)row * 128u + (uint32_t)((lc ^ (row & 7)) << 4);
            cp16(s0 + d,              g_xh + (size_t)(mbase + row) * K_TOT + gk);
            cp16(s0 + TILE_BYTES + d, g_wh + (size_t)(nbase + row) * K_TOT + gk);
        }
    };

    float acc[4][4][4];
#pragma unroll
    for (int a = 0; a < 4; a++)
#pragma unroll
        for (int b = 0; b < 4; b++)
#pragma unroll
            for (int c = 0; c < 4; c++) acc[a][b][c] = 0.0f;

    load_stage(0, 0); cp_commit();
    load_stage(1, 1); cp_commit();

    // ldmatrix addressing (lane-dependent parts)
    const uint32_t a_lrow  = (uint32_t)(lane & 15);
    const uint32_t a_lchnk = (uint32_t)(lane >> 4);          // 0/1 -> k half
    const uint32_t b_lrow  = (uint32_t)((lane & 7) + ((lane >> 4) << 3));
    const uint32_t b_lchnk = (uint32_t)((lane >> 3) & 1);

    int stg = 0;
#pragma unroll 1
    for (int kt = 0; kt < NK; kt++) {
        cp_wait<1>();
        __syncthreads();
        if (kt + 2 < NK) {
            int ns = stg + 2; if (ns >= NSTAGE) ns -= NSTAGE;
            load_stage(kt + 2, ns);
        }
        cp_commit();

        const uint32_t base = sb + stg * STAGE_BYTES;
#pragma unroll
        for (int s = 0; s < 4; s++) {                       // four k16 slices of BK=64
            uint32_t ah[4][4];
            const uint32_t achunk = 2u * s + a_lchnk;
#pragma unroll
            for (int mf = 0; mf < 4; mf++) {
                const uint32_t row = (uint32_t)(wm * 64 + mf * 16) + a_lrow;
                const uint32_t addr = base + row * 128u + ((achunk ^ (row & 7)) << 4);
                ldsm_x4(ah[mf], addr);
            }
            uint32_t bh[8];
            const uint32_t bchunk = 2u * s + b_lchnk;
#pragma unroll
            for (int p = 0; p < 2; p++) {
                const uint32_t row = (uint32_t)(wn * 32 + p * 16) + b_lrow;
                const uint32_t addr = base + TILE_BYTES + row * 128u + ((bchunk ^ (row & 7)) << 4);
                ldsm_x4(&bh[p * 4], addr);
            }
#pragma unroll
            for (int mf = 0; mf < 4; mf++) {
#pragma unroll
                for (int nf = 0; nf < 4; nf++) {
                    const int p = nf >> 1, q = nf & 1;
                    mma_f16(acc[mf][nf], ah[mf], bh[p * 4 + 2 * q], bh[p * 4 + 2 * q + 1]);
                }
            }
        }
        stg++; if (stg >= NSTAGE) stg = 0;
    }

    // ------------------- epilogue -------------------
    const int gid = lane >> 2;          // 0..7 (row in frag)
    const int tg  = lane & 3;           // 0..3 (col pair)
    float* ob = out + (size_t)mbase * N_TOT + nbase;
#pragma unroll
    for (int mf = 0; mf < 4; mf++) {
#pragma unroll
        for (int nf = 0; nf < 4; nf++) {
            const int r = wm * 64 + mf * 16 + gid;
            const int c = wn * 32 + nf * 8 + tg * 2;
            *reinterpret_cast<float2*>(ob + (size_t)r * N_TOT + c) =
                make_float2(acc[mf][nf][0], acc[mf][nf][1]);
            *reinterpret_cast<float2*>(ob + (size_t)(r + 8) * N_TOT + c) =
                make_float2(acc[mf][nf][2], acc[mf][nf][3]);
        }
    }
}

// ------------------- launch -------------------
extern "C" void kernel_launch(void* const* d_in, const int* in_sizes, int n_in,
                              void* d_out, int out_size) {
    const float* x = (const float*)d_in[0];
    const float* w = (const float*)d_in[1];
    // robustness: identify tensors by element count (x: 8192*4096=33.5M, w: 4096*4096=16.8M)
    if (n_in >= 2 && in_sizes[0] == N_TOT * K_TOT) {
        x = (const float*)d_in[1];
        w = (const float*)d_in[0];
    }
    float* out = (float*)d_out;

    __half *xh, *wh;
    cudaGetSymbolAddress((void**)&xh, g_xh);
    cudaGetSymbolAddress((void**)&wh, g_wh);

    prep_kernel<<<(int)(((size_t)M_TOT * K_TOT / 8) / 256), 256>>>(x, xh);
    prep_kernel<<<(int)(((size_t)N_TOT * K_TOT / 8) / 256), 256>>>(w, wh);

    cudaFuncSetAttribute(gemm_fp16_kernel,
                         cudaFuncAttributeMaxDynamicSharedMemorySize, SMEM_TOTAL);
    gemm_fp16_kernel<<<dim3(N_TOT / BN, M_TOT / BM), 256, SMEM_TOTAL>>>(out);
}